// round 4
// baseline (speedup 1.0000x reference)
#include <cuda_runtime.h>
#include <cuda_bf16.h>
#include <cstdint>

// ============================================================================
// Problem constants
// ============================================================================
static constexpr int M_TOTAL = 8192;
static constexpr int N_TOTAL = 4096;
static constexpr int K_TOTAL = 4096;
static constexpr int RANK    = 8;

// GEMM tiling
static constexpr int BM = 128;
static constexpr int BN = 128;
static constexpr int BK = 128;                 // 128 int8 = 128 bytes per row
static constexpr int NSTAGES = 3;
static constexpr int KT = K_TOTAL / BK;        // 32 k-iterations
static constexpr int THREADS = 256;            // 8 warps: 2 (M) x 4 (N)

static constexpr int A_TILE_BYTES = BM * BK;               // 16384
static constexpr int B_TILE_BYTES = BN * BK;               // 16384
static constexpr int STAGE_BYTES  = A_TILE_BYTES + B_TILE_BYTES;   // 32768
static constexpr int SMEM_TOTAL   = NSTAGES * STAGE_BYTES; // 98304

// epilogue staging: 128 rows x 132 floats (pad 4) = 67584 B <= SMEM_TOTAL
static constexpr int EPI_STRIDE = 132;

// XOR swizzle for 128B rows: 16B chunk index ^= (row & 7)
#define SMEM_SWIZZLE_128B(byte_offset) \
    ((byte_offset) ^ (((byte_offset) >> 3) & 0x70))

// ============================================================================
// Scratch (no cudaMalloc allowed)
// ============================================================================
__device__ __align__(1024) int8_t g_xq[(size_t)M_TOTAL * K_TOTAL];  // 32 MB
__device__ __align__(1024) int8_t g_wq[(size_t)N_TOTAL * K_TOTAL];  // 16 MB

// ============================================================================
// PTX helpers (baseline ISA only)
// ============================================================================
__device__ __forceinline__ uint32_t smem_to_u32(const void* p) {
    uint32_t a;
    asm("{ .reg .u64 t; cvta.to.shared.u64 t, %1; cvt.u32.u64 %0, t; }" : "=r"(a) : "l"(p));
    return a;
}

__device__ __forceinline__ void cp_async16(uint32_t smem_addr, const void* gptr) {
    asm volatile("cp.async.cg.shared.global [%0], [%1], 16;"
                 :: "r"(smem_addr), "l"(gptr) : "memory");
}

__device__ __forceinline__ void ldsm_x4(uint32_t* r, uint32_t addr) {
    asm volatile("ldmatrix.sync.aligned.m8n8.x4.shared.b16 {%0,%1,%2,%3}, [%4];"
                 : "=r"(r[0]), "=r"(r[1]), "=r"(r[2]), "=r"(r[3]) : "r"(addr));
}

// NOTE: non-volatile — lets ptxas interleave independent MMAs with later LDSMs
__device__ __forceinline__ void mma_s8(int* d, const uint32_t* a, const uint32_t* b) {
    asm("mma.sync.aligned.m16n8k32.row.col.s32.s8.s8.s32 "
        "{%0,%1,%2,%3}, {%4,%5,%6,%7}, {%8,%9}, {%0,%1,%2,%3};"
        : "+r"(d[0]), "+r"(d[1]), "+r"(d[2]), "+r"(d[3])
        : "r"(a[0]), "r"(a[1]), "r"(a[2]), "r"(a[3]), "r"(b[0]), "r"(b[1]));
}

__device__ __forceinline__ int qdq_int(float x, float s) {
    return (int)rintf(fminf(fmaxf(x / s, -8.0f), 7.0f));
}

__device__ __forceinline__ uint32_t pack4(int q0, int q1, int q2, int q3) {
    return (uint32_t)(q0 & 0xff) | ((uint32_t)(q1 & 0xff) << 8) |
           ((uint32_t)(q2 & 0xff) << 16) | ((uint32_t)(q3 & 0xff) << 24);
}

// ============================================================================
// Prep 1: quantize x -> int8 (16 elems / thread)
// ============================================================================
__global__ void quant_x_kernel(const float* __restrict__ x,
                               const float* __restrict__ tscales,
                               const int* __restrict__ step) {
    size_t t = (size_t)blockIdx.x * blockDim.x + threadIdx.x;
    float s = tscales[step[0]];
    const float4* x4 = reinterpret_cast<const float4*>(x) + t * 4;
    uint4 o;
    {   float4 v = x4[0];
        o.x = pack4(qdq_int(v.x, s), qdq_int(v.y, s), qdq_int(v.z, s), qdq_int(v.w, s)); }
    {   float4 v = x4[1];
        o.y = pack4(qdq_int(v.x, s), qdq_int(v.y, s), qdq_int(v.z, s), qdq_int(v.w, s)); }
    {   float4 v = x4[2];
        o.z = pack4(qdq_int(v.x, s), qdq_int(v.y, s), qdq_int(v.z, s), qdq_int(v.w, s)); }
    {   float4 v = x4[3];
        o.w = pack4(qdq_int(v.x, s), qdq_int(v.y, s), qdq_int(v.z, s), qdq_int(v.w, s)); }
    reinterpret_cast<uint4*>(g_xq)[t] = o;
}

// ============================================================================
// Prep 2: merged weight (W + B@A), quantize -> int8 (16 elems / thread)
// ============================================================================
__global__ void quant_w_kernel(const float* __restrict__ W,
                               const float* __restrict__ A,   // [RANK, K]
                               const float* __restrict__ B,   // [N, RANK]
                               const float* __restrict__ ws) {
    size_t t = (size_t)blockIdx.x * blockDim.x + threadIdx.x;
    int o  = (int)(t >> 8);
    int g0 = (int)(t & 255) * 4;

    float4 w[4];
    #pragma unroll
    for (int g = 0; g < 4; g++)
        w[g] = reinterpret_cast<const float4*>(W)[(size_t)o * 1024 + g0 + g];

    #pragma unroll
    for (int r = 0; r < RANK; r++) {
        float br = B[o * RANK + r];
        #pragma unroll
        for (int g = 0; g < 4; g++) {
            float4 a = reinterpret_cast<const float4*>(A)[(size_t)r * 1024 + g0 + g];
            w[g].x += br * a.x; w[g].y += br * a.y;
            w[g].z += br * a.z; w[g].w += br * a.w;
        }
    }
    float s = ws[o];
    uint4 outv;
    outv.x = pack4(qdq_int(w[0].x, s), qdq_int(w[0].y, s), qdq_int(w[0].z, s), qdq_int(w[0].w, s));
    outv.y = pack4(qdq_int(w[1].x, s), qdq_int(w[1].y, s), qdq_int(w[1].z, s), qdq_int(w[1].w, s));
    outv.z = pack4(qdq_int(w[2].x, s), qdq_int(w[2].y, s), qdq_int(w[2].z, s), qdq_int(w[2].w, s));
    outv.w = pack4(qdq_int(w[3].x, s), qdq_int(w[3].y, s), qdq_int(w[3].z, s), qdq_int(w[3].w, s));
    reinterpret_cast<uint4*>(g_wq)[t] = outv;
}

// ============================================================================
// GEMM
// ============================================================================
__device__ __forceinline__ void load_stage(uint32_t sb, int it,
                                           const char* gA, const char* gB, int tid) {
    int s = it % NSTAGES;
    int kk = it * BK;
    uint32_t abase = sb + s * STAGE_BYTES;
    uint32_t bbase = abase + A_TILE_BYTES;
    #pragma unroll
    for (int j = 0; j < 4; j++) {
        int ch = tid + j * THREADS;
        int row = ch >> 3, c = ch & 7;
        cp_async16(abase + SMEM_SWIZZLE_128B(row * 128 + c * 16),
                   gA + (size_t)row * K_TOTAL + kk + c * 16);
    }
    #pragma unroll
    for (int j = 0; j < 4; j++) {
        int ch = tid + j * THREADS;
        int row = ch >> 3, c = ch & 7;
        cp_async16(bbase + SMEM_SWIZZLE_128B(row * 128 + c * 16),
                   gB + (size_t)row * K_TOTAL + kk + c * 16);
    }
    asm volatile("cp.async.commit_group;" ::: "memory");
}

__global__ void __launch_bounds__(THREADS, 2)
gemm_kernel(const float* __restrict__ ws,
            const float* __restrict__ bias,
            const float* __restrict__ tscales,
            const int* __restrict__ step,
            float* __restrict__ out) {
    extern __shared__ char smem[];
    uint32_t sb = smem_to_u32(smem);
    int tid  = threadIdx.x;
    int lane = tid & 31;
    int warp = tid >> 5;
    int wm   = warp >> 2;     // 0..1 -> 64-row slab
    int wn   = warp & 3;      // 0..3 -> 32-col slab

    const int n_tiles = N_TOTAL / BN;          // 32
    int nt = blockIdx.x & (n_tiles - 1);
    int mt = blockIdx.x / n_tiles;
    int m0 = mt * BM;
    int n0 = nt * BN;

    const char* gA = reinterpret_cast<const char*>(g_xq) + (size_t)m0 * K_TOTAL;
    const char* gB = reinterpret_cast<const char*>(g_wq) + (size_t)n0 * K_TOTAL;

    // ldmatrix per-lane addressing
    int rowA = lane & 15;
    int cA   = lane >> 4;
    int rowB = (lane & 7) + ((lane >> 4) << 3);
    int cB   = (lane >> 3) & 1;

    uint32_t aLaneOff = (uint32_t)(wm * 64 + rowA) * 128;
    uint32_t bLaneOff = (uint32_t)(wn * 32 + rowB) * 128;
    int swA = rowA & 7;
    int swB = rowB & 7;

    int acc[4][4][4];
    #pragma unroll
    for (int i = 0; i < 4; i++)
        #pragma unroll
        for (int j = 0; j < 4; j++)
            #pragma unroll
            for (int k = 0; k < 4; k++) acc[i][j][k] = 0;

    load_stage(sb, 0, gA, gB, tid);
    load_stage(sb, 1, gA, gB, tid);

    for (int it = 0; it < KT; ++it) {
        int s = it % NSTAGES;
        if (it < KT - 1) asm volatile("cp.async.wait_group 1;" ::: "memory");
        else             asm volatile("cp.async.wait_group 0;" ::: "memory");
        __syncthreads();
        if (it + 2 < KT) load_stage(sb, it + 2, gA, gB, tid);

        uint32_t abase = sb + s * STAGE_BYTES + aLaneOff;
        uint32_t bbase = sb + s * STAGE_BYTES + A_TILE_BYTES + bLaneOff;

        #pragma unroll
        for (int kstep = 0; kstep < 4; kstep++) {
            // B fragments for this kstep: 8 regs
            uint32_t bfrag[4][2];
            #pragma unroll
            for (int nt2 = 0; nt2 < 2; nt2++) {
                uint32_t r[4];
                ldsm_x4(r, bbase + (uint32_t)(nt2 * 16 * 128) +
                           (uint32_t)(((kstep * 2 + cB) ^ swB) * 16));
                bfrag[nt2 * 2 + 0][0] = r[0]; bfrag[nt2 * 2 + 0][1] = r[1];
                bfrag[nt2 * 2 + 1][0] = r[2]; bfrag[nt2 * 2 + 1][1] = r[3];
            }
            // A fragments loaded 4 regs at a time -> low live-register count
            #pragma unroll
            for (int mi = 0; mi < 4; mi++) {
                uint32_t afrag[4];
                ldsm_x4(afrag, abase + (uint32_t)(mi * 16 * 128) +
                               (uint32_t)(((kstep * 2 + cA) ^ swA) * 16));
                #pragma unroll
                for (int ni = 0; ni < 4; ni++)
                    mma_s8(acc[mi][ni], afrag, bfrag[ni]);
            }
        }
    }

    // ---- epilogue: scale + bias into padded smem, then coalesced STG ----
    float sx = tscales[step[0]];
    int r0 = lane >> 2;
    int c0 = (lane & 3) * 2;

    float scl0[4], scl1[4], bs0[4], bs1[4];
    #pragma unroll
    for (int ni = 0; ni < 4; ni++) {
        int gn = n0 + wn * 32 + ni * 8 + c0;
        scl0[ni] = sx * ws[gn];
        scl1[ni] = sx * ws[gn + 1];
        bs0[ni]  = bias[gn];
        bs1[ni]  = bias[gn + 1];
    }

    __syncthreads();   // pipeline drained (wait_group 0 above); smem reusable
    float* smf = reinterpret_cast<float*>(smem);
    #pragma unroll
    for (int mi = 0; mi < 4; mi++) {
        #pragma unroll
        for (int h = 0; h < 2; h++) {
            int row = wm * 64 + mi * 16 + r0 + h * 8;
            #pragma unroll
            for (int ni = 0; ni < 4; ni++) {
                int col = wn * 32 + ni * 8 + c0;
                float2 v;
                v.x = __int2float_rn(acc[mi][ni][h * 2 + 0]) * scl0[ni] + bs0[ni];
                v.y = __int2float_rn(acc[mi][ni][h * 2 + 1]) * scl1[ni] + bs1[ni];
                *reinterpret_cast<float2*>(smf + row * EPI_STRIDE + col) = v;
            }
        }
    }
    __syncthreads();

    // each warp writes 16 rows, 512B coalesced per row
    #pragma unroll
    for (int i = 0; i < 16; i++) {
        int row = warp * 16 + i;
        float4 v = *reinterpret_cast<float4*>(smf + row * EPI_STRIDE + lane * 4);
        *reinterpret_cast<float4*>(out + (size_t)(m0 + row) * N_TOTAL + n0 + lane * 4) = v;
    }
}

// ============================================================================
// Launch
// ============================================================================
extern "C" void kernel_launch(void* const* d_in, const int* in_sizes, int n_in,
                              void* d_out, int out_size) {
    const float* x    = (const float*)d_in[0];
    const float* W    = (const float*)d_in[1];
    const float* A    = (const float*)d_in[2];
    const float* B    = (const float*)d_in[3];
    const float* ws   = (const float*)d_in[4];
    const float* ts   = (const float*)d_in[5];
    const float* bias = (const float*)d_in[6];
    const int*   step = (const int*)d_in[7];
    float* out = (float*)d_out;

    quant_x_kernel<<<(M_TOTAL * K_TOTAL / 16) / 256, 256>>>(x, ts, step);
    quant_w_kernel<<<(N_TOTAL * K_TOTAL / 16) / 256, 256>>>(W, A, B, ws);

    static bool attr_set = false;
    if (!attr_set) {
        cudaFuncSetAttribute(gemm_kernel, cudaFuncAttributeMaxDynamicSharedMemorySize, SMEM_TOTAL);
        attr_set = true;
    }
    int grid = (M_TOTAL / BM) * (N_TOTAL / BN);   // 2048
    gemm_kernel<<<grid, THREADS, SMEM_TOTAL>>>(ws, bias, ts, step, out);
}

// round 5
// speedup vs baseline: 2.8093x; 2.8093x over previous
#include <cuda_runtime.h>
#include <cuda_bf16.h>
#include <cstdint>

// ============================================================================
// Problem constants
// ============================================================================
static constexpr int M_TOTAL = 8192;
static constexpr int N_TOTAL = 4096;
static constexpr int K_TOTAL = 4096;
static constexpr int RANK    = 8;

// GEMM tiling (byte-oriented: BK = 128 BYTES = 64 bf16)
static constexpr int BM = 128;
static constexpr int BN = 128;
static constexpr int BK_BYTES = 128;
static constexpr int K_BYTES  = K_TOTAL * 2;               // bf16 row bytes
static constexpr int NSTAGES  = 3;
static constexpr int KT = K_BYTES / BK_BYTES;              // 64 k-iterations
static constexpr int THREADS = 256;                        // 8 warps: 2 (M) x 4 (N)

static constexpr int A_TILE_BYTES = BM * BK_BYTES;         // 16384
static constexpr int B_TILE_BYTES = BN * BK_BYTES;         // 16384
static constexpr int STAGE_BYTES  = A_TILE_BYTES + B_TILE_BYTES;   // 32768
static constexpr int SMEM_TOTAL   = NSTAGES * STAGE_BYTES; // 98304

// epilogue staging: 128 rows x 132 floats (pad 4) = 67584 B <= SMEM_TOTAL
static constexpr int EPI_STRIDE = 132;

// XOR swizzle for 128B rows: 16B chunk index ^= (row & 7)
#define SMEM_SWIZZLE_128B(byte_offset) \
    ((byte_offset) ^ (((byte_offset) >> 3) & 0x70))

// ============================================================================
// Scratch (no cudaMalloc allowed): quantized integer values stored as bf16
// ============================================================================
__device__ __align__(1024) __nv_bfloat16 g_xq[(size_t)M_TOTAL * K_TOTAL];  // 64 MB
__device__ __align__(1024) __nv_bfloat16 g_wq[(size_t)N_TOTAL * K_TOTAL];  // 32 MB

// ============================================================================
// PTX helpers (baseline ISA only)
// ============================================================================
__device__ __forceinline__ uint32_t smem_to_u32(const void* p) {
    uint32_t a;
    asm("{ .reg .u64 t; cvta.to.shared.u64 t, %1; cvt.u32.u64 %0, t; }" : "=r"(a) : "l"(p));
    return a;
}

__device__ __forceinline__ void cp_async16(uint32_t smem_addr, const void* gptr) {
    asm volatile("cp.async.cg.shared.global [%0], [%1], 16;"
                 :: "r"(smem_addr), "l"(gptr) : "memory");
}

__device__ __forceinline__ void ldsm_x4(uint32_t* r, uint32_t addr) {
    asm volatile("ldmatrix.sync.aligned.m8n8.x4.shared.b16 {%0,%1,%2,%3}, [%4];"
                 : "=r"(r[0]), "=r"(r[1]), "=r"(r[2]), "=r"(r[3]) : "r"(addr));
}

// bf16 HMMA, fp32 accumulate (exact for integer operands in [-8,7], K<=4096)
__device__ __forceinline__ void mma_bf16(float* d, const uint32_t* a, const uint32_t* b) {
    asm("mma.sync.aligned.m16n8k16.row.col.f32.bf16.bf16.f32 "
        "{%0,%1,%2,%3}, {%4,%5,%6,%7}, {%8,%9}, {%0,%1,%2,%3};"
        : "+f"(d[0]), "+f"(d[1]), "+f"(d[2]), "+f"(d[3])
        : "r"(a[0]), "r"(a[1]), "r"(a[2]), "r"(a[3]), "r"(b[0]), "r"(b[1]));
}

__device__ __forceinline__ float qdq_int(float x, float s) {
    // integer part of LSQ qdq; rintf = round-half-even (== jnp.round)
    return rintf(fminf(fmaxf(x / s, -8.0f), 7.0f));
}

__device__ __forceinline__ uint32_t pack2bf(float a, float b) {
    __nv_bfloat162 p = __floats2bfloat162_rn(a, b);
    return *reinterpret_cast<uint32_t*>(&p);
}

// ============================================================================
// Prep 1: quantize x -> bf16 integers (8 elems / thread, 16B out)
// ============================================================================
__global__ void quant_x_kernel(const float* __restrict__ x,
                               const float* __restrict__ tscales,
                               const int* __restrict__ step) {
    size_t t = (size_t)blockIdx.x * blockDim.x + threadIdx.x;
    float s = tscales[step[0]];
    const float4* x4 = reinterpret_cast<const float4*>(x) + t * 2;
    float4 v0 = x4[0];
    float4 v1 = x4[1];
    uint4 o;
    o.x = pack2bf(qdq_int(v0.x, s), qdq_int(v0.y, s));
    o.y = pack2bf(qdq_int(v0.z, s), qdq_int(v0.w, s));
    o.z = pack2bf(qdq_int(v1.x, s), qdq_int(v1.y, s));
    o.w = pack2bf(qdq_int(v1.z, s), qdq_int(v1.w, s));
    reinterpret_cast<uint4*>(g_xq)[t] = o;
}

// ============================================================================
// Prep 2: merged weight (W + B@A), quantize -> bf16 integers (8 elems / thread)
// ============================================================================
__global__ void quant_w_kernel(const float* __restrict__ W,
                               const float* __restrict__ A,   // [RANK, K]
                               const float* __restrict__ B,   // [N, RANK]
                               const float* __restrict__ ws) {
    size_t t = (size_t)blockIdx.x * blockDim.x + threadIdx.x;
    int o  = (int)(t >> 9);               // 512 threads of 8 elems per row (K=4096)
    int g0 = (int)(t & 511) * 2;          // float4 index within row

    float4 w[2];
    w[0] = reinterpret_cast<const float4*>(W)[(size_t)o * 1024 + g0];
    w[1] = reinterpret_cast<const float4*>(W)[(size_t)o * 1024 + g0 + 1];

    #pragma unroll
    for (int r = 0; r < RANK; r++) {
        float br = B[o * RANK + r];
        #pragma unroll
        for (int g = 0; g < 2; g++) {
            float4 a = reinterpret_cast<const float4*>(A)[(size_t)r * 1024 + g0 + g];
            w[g].x += br * a.x; w[g].y += br * a.y;
            w[g].z += br * a.z; w[g].w += br * a.w;
        }
    }
    float s = ws[o];
    uint4 outv;
    outv.x = pack2bf(qdq_int(w[0].x, s), qdq_int(w[0].y, s));
    outv.y = pack2bf(qdq_int(w[0].z, s), qdq_int(w[0].w, s));
    outv.z = pack2bf(qdq_int(w[1].x, s), qdq_int(w[1].y, s));
    outv.w = pack2bf(qdq_int(w[1].z, s), qdq_int(w[1].w, s));
    reinterpret_cast<uint4*>(g_wq)[t] = outv;
}

// ============================================================================
// GEMM: out[m,n] = (sum_k qx[m,k]*qw[n,k]) * sx*ws[n] + bias[n]
// 128x128 CTA tile, 3-stage cp.async pipeline, mma.sync bf16 (exact f32 accum)
// ============================================================================
__device__ __forceinline__ void load_stage(uint32_t sb, int it,
                                           const char* gA, const char* gB, int tid) {
    int s = it % NSTAGES;
    int kk = it * BK_BYTES;
    uint32_t abase = sb + s * STAGE_BYTES;
    uint32_t bbase = abase + A_TILE_BYTES;
    #pragma unroll
    for (int j = 0; j < 4; j++) {
        int ch = tid + j * THREADS;            // 0..1023
        int row = ch >> 3, c = ch & 7;
        cp_async16(abase + SMEM_SWIZZLE_128B(row * 128 + c * 16),
                   gA + (size_t)row * K_BYTES + kk + c * 16);
    }
    #pragma unroll
    for (int j = 0; j < 4; j++) {
        int ch = tid + j * THREADS;
        int row = ch >> 3, c = ch & 7;
        cp_async16(bbase + SMEM_SWIZZLE_128B(row * 128 + c * 16),
                   gB + (size_t)row * K_BYTES + kk + c * 16);
    }
    asm volatile("cp.async.commit_group;" ::: "memory");
}

__global__ void __launch_bounds__(THREADS, 2)
gemm_kernel(const float* __restrict__ ws,
            const float* __restrict__ bias,
            const float* __restrict__ tscales,
            const int* __restrict__ step,
            float* __restrict__ out) {
    extern __shared__ char smem[];
    uint32_t sb = smem_to_u32(smem);
    int tid  = threadIdx.x;
    int lane = tid & 31;
    int warp = tid >> 5;
    int wm   = warp >> 2;     // 0..1 -> 64-row slab
    int wn   = warp & 3;      // 0..3 -> 32-col slab

    const int n_tiles = N_TOTAL / BN;          // 32
    int nt = blockIdx.x & (n_tiles - 1);
    int mt = blockIdx.x / n_tiles;
    int m0 = mt * BM;
    int n0 = nt * BN;

    const char* gA = reinterpret_cast<const char*>(g_xq) + (size_t)m0 * K_BYTES;
    const char* gB = reinterpret_cast<const char*>(g_wq) + (size_t)n0 * K_BYTES;

    // ldmatrix per-lane addressing (32B consumed per kstep: two 16B chunks)
    int rowA = lane & 15;
    int cA   = lane >> 4;
    int rowB = (lane & 7) + ((lane >> 4) << 3);
    int cB   = (lane >> 3) & 1;

    uint32_t aLaneOff = (uint32_t)(wm * 64 + rowA) * 128;
    uint32_t bLaneOff = (uint32_t)(wn * 32 + rowB) * 128;
    int swA = rowA & 7;
    int swB = rowB & 7;

    float acc[4][4][4];
    #pragma unroll
    for (int i = 0; i < 4; i++)
        #pragma unroll
        for (int j = 0; j < 4; j++)
            #pragma unroll
            for (int k = 0; k < 4; k++) acc[i][j][k] = 0.0f;

    load_stage(sb, 0, gA, gB, tid);
    load_stage(sb, 1, gA, gB, tid);

    for (int it = 0; it < KT; ++it) {
        int s = it % NSTAGES;
        if (it < KT - 1) asm volatile("cp.async.wait_group 1;" ::: "memory");
        else             asm volatile("cp.async.wait_group 0;" ::: "memory");
        __syncthreads();
        if (it + 2 < KT) load_stage(sb, it + 2, gA, gB, tid);

        uint32_t abase = sb + s * STAGE_BYTES + aLaneOff;
        uint32_t bbase = sb + s * STAGE_BYTES + A_TILE_BYTES + bLaneOff;

        #pragma unroll
        for (int kstep = 0; kstep < 4; kstep++) {
            // B fragments for this kstep (two ldsm_x4 -> four n8 tiles)
            uint32_t bfrag[4][2];
            #pragma unroll
            for (int nt2 = 0; nt2 < 2; nt2++) {
                uint32_t r[4];
                ldsm_x4(r, bbase + (uint32_t)(nt2 * 16 * 128) +
                           (uint32_t)(((kstep * 2 + cB) ^ swB) * 16));
                bfrag[nt2 * 2 + 0][0] = r[0]; bfrag[nt2 * 2 + 0][1] = r[1];
                bfrag[nt2 * 2 + 1][0] = r[2]; bfrag[nt2 * 2 + 1][1] = r[3];
            }
            #pragma unroll
            for (int mi = 0; mi < 4; mi++) {
                uint32_t afrag[4];
                ldsm_x4(afrag, abase + (uint32_t)(mi * 16 * 128) +
                               (uint32_t)(((kstep * 2 + cA) ^ swA) * 16));
                #pragma unroll
                for (int ni = 0; ni < 4; ni++)
                    mma_bf16(acc[mi][ni], afrag, bfrag[ni]);
            }
        }
    }

    // ---- epilogue: scale + bias into padded smem, then coalesced STG ----
    float sx = tscales[step[0]];
    int r0 = lane >> 2;
    int c0 = (lane & 3) * 2;

    float scl0[4], scl1[4], bs0[4], bs1[4];
    #pragma unroll
    for (int ni = 0; ni < 4; ni++) {
        int gn = n0 + wn * 32 + ni * 8 + c0;
        scl0[ni] = sx * ws[gn];
        scl1[ni] = sx * ws[gn + 1];
        bs0[ni]  = bias[gn];
        bs1[ni]  = bias[gn + 1];
    }

    __syncthreads();   // pipeline drained; smem reusable
    float* smf = reinterpret_cast<float*>(smem);
    #pragma unroll
    for (int mi = 0; mi < 4; mi++) {
        #pragma unroll
        for (int h = 0; h < 2; h++) {
            int row = wm * 64 + mi * 16 + r0 + h * 8;
            #pragma unroll
            for (int ni = 0; ni < 4; ni++) {
                int col = wn * 32 + ni * 8 + c0;
                float2 v;
                v.x = fmaf(acc[mi][ni][h * 2 + 0], scl0[ni], bs0[ni]);
                v.y = fmaf(acc[mi][ni][h * 2 + 1], scl1[ni], bs1[ni]);
                *reinterpret_cast<float2*>(smf + row * EPI_STRIDE + col) = v;
            }
        }
    }
    __syncthreads();

    // each warp writes 16 rows, 512B coalesced per row
    #pragma unroll
    for (int i = 0; i < 16; i++) {
        int row = warp * 16 + i;
        float4 v = *reinterpret_cast<float4*>(smf + row * EPI_STRIDE + lane * 4);
        *reinterpret_cast<float4*>(out + (size_t)(m0 + row) * N_TOTAL + n0 + lane * 4) = v;
    }
}

// ============================================================================
// Launch
// ============================================================================
extern "C" void kernel_launch(void* const* d_in, const int* in_sizes, int n_in,
                              void* d_out, int out_size) {
    const float* x    = (const float*)d_in[0];
    const float* W    = (const float*)d_in[1];
    const float* A    = (const float*)d_in[2];
    const float* B    = (const float*)d_in[3];
    const float* ws   = (const float*)d_in[4];
    const float* ts   = (const float*)d_in[5];
    const float* bias = (const float*)d_in[6];
    const int*   step = (const int*)d_in[7];
    float* out = (float*)d_out;

    quant_x_kernel<<<(M_TOTAL * K_TOTAL / 8) / 256, 256>>>(x, ts, step);
    quant_w_kernel<<<(N_TOTAL * K_TOTAL / 8) / 256, 256>>>(W, A, B, ws);

    static bool attr_set = false;
    if (!attr_set) {
        cudaFuncSetAttribute(gemm_kernel, cudaFuncAttributeMaxDynamicSharedMemorySize, SMEM_TOTAL);
        attr_set = true;
    }
    int grid = (M_TOTAL / BM) * (N_TOTAL / BN);   // 2048
    gemm_kernel<<<grid, THREADS, SMEM_TOTAL>>>(ws, bias, ts, step, out);
}